// round 14
// baseline (speedup 1.0000x reference)
#include <cuda_runtime.h>
#include <math.h>

#define TILE 16              // 16x16 pixel tile per raster block
#define SUPT 4               // tiles per supertile edge (64 px)
#define NTHREADS 128         // 2 pixels per thread (rows ly, ly+8)
#define NW 4
#define MAX_G 2048
#define MAX_SUP 256
#define MAH_CUT 37.0f
#define LOG2E 1.4426950408889634f

// ---- depth-sorted packed gaussians (Phase A output) ----
__device__ float4 g_pA[MAX_G];   // mx, my, cullR^2, a' (= -0.5*iA*log2e)
__device__ float4 g_pB[MAX_G];   // b' (= -iB*log2e), c' (= -0.5*iC*log2e), log2(opac), colR
__device__ float2 g_pC[MAX_G];   // colG, colB

// ---- per-supertile depth-ordered candidate indices (Phase B output) ----
__device__ int s_cand[MAX_SUP * MAX_G];
__device__ int s_cnt[MAX_SUP];

// ---- software grid barrier (replay-safe: generation is monotonic) ----
__device__ unsigned g_bar_count = 0;
__device__ volatile unsigned g_bar_gen = 0;

__device__ __forceinline__ void grid_barrier(unsigned nblocks) {
    __syncthreads();
    if (threadIdx.x == 0) {
        unsigned gen = g_bar_gen;
        __threadfence();
        unsigned old = atomicAdd(&g_bar_count, 1u);
        if (old == nblocks - 1u) {
            g_bar_count = 0;
            __threadfence();
            g_bar_gen = gen + 1u;
        } else {
            while (g_bar_gen == gen) __nanosleep(32);
        }
        __threadfence();
    }
    __syncthreads();
}

__device__ __forceinline__ float ex2(float x) {
    float r;
    asm("ex2.approx.ftz.f32 %0, %1;" : "=f"(r) : "f"(x));
    return r;
}

__global__ void __launch_bounds__(NTHREADS, 8) fused_kernel(
        const float* __restrict__ means,
        const float* __restrict__ log_scale,
        const float* __restrict__ rot,
        const float* __restrict__ colour_logits,
        const float* __restrict__ opacity_logit,
        const float* __restrict__ depth,
        int G, int W, int H, int ntx, int ntiles, int nsx, int nsup,
        float* __restrict__ out) {
    int tid  = threadIdx.x;
    int wid  = tid >> 5;
    int lane = tid & 31;
    unsigned lmask = (1u << lane) - 1u;

    __shared__ float sd[MAX_G];        // Phase A depth stage
    __shared__ float4 sA[NTHREADS];    // Phase C compacted gaussians
    __shared__ float4 sB[NTHREADS];
    __shared__ float  sC[NTHREADS];
    __shared__ int    scnt[16];        // Phase B: [round][warp]; Phase C: [warp]

    // ================= Phase A: rank + preprocess (blocks 0..255) =========
    if (blockIdx.x < 256) {
        for (int j = tid; j < G; j += NTHREADS) sd[j] = depth[j];
        __syncthreads();
        for (int i = blockIdx.x * NW + wid; i < G; i += 256 * NW) {
            float di = sd[i];
            int r = 0;
            for (int j = lane; j < G; j += 32) {
                float dj = sd[j];
                r += (dj < di) || (dj == di && j < i);
            }
            r = __reduce_add_sync(0xffffffffu, r);

            if (lane == 0) {
                float s2x = __expf(2.f * log_scale[2 * i + 0]);
                float s2y = __expf(2.f * log_scale[2 * i + 1]);
                float s, c;
                __sincosf(rot[i], &s, &c);

                float ca = c * c * s2x + s * s * s2y;
                float cb = c * s * (s2x - s2y);
                float cd = s * s * s2x + c * c * s2y;
                float det = ca * cd - cb * cb;
                float inv = 1.f / det;
                float iA = cd * inv;
                float iB = -cb * inv;
                float iC = ca * inv;

                float opac = 1.f / (1.f + __expf(-opacity_logit[i]));
                float cr  = 1.f / (1.f + __expf(-colour_logits[3 * i + 0]));
                float cg  = 1.f / (1.f + __expf(-colour_logits[3 * i + 1]));
                float cbl = 1.f / (1.f + __expf(-colour_logits[3 * i + 2]));

                float tr = 0.5f * (ca + cd);
                float lmax = tr + sqrtf(fmaxf(tr * tr - det, 0.f));

                g_pA[r] = make_float4(means[2 * i + 0], means[2 * i + 1],
                                      MAH_CUT * lmax, -0.5f * iA * LOG2E);
                g_pB[r] = make_float4(-iB * LOG2E, -0.5f * iC * LOG2E,
                                      __log2f(opac), cr);
                g_pC[r] = make_float2(cg, cbl);
            }
        }
    }

    grid_barrier(gridDim.x);

    // ================= Phase B: supertile binning (blocks 0..nsup-1) ======
    // Batched: 4 rounds per chunk, ONE barrier for the (round,warp) prefix.
    if (blockIdx.x < (unsigned)nsup) {
        int st = blockIdx.x;
        float sx0 = (float)((st % nsx) * (TILE * SUPT));
        float sy0 = (float)((st / nsx) * (TILE * SUPT));
        float sx1 = sx0 + (float)(TILE * SUPT - 1);
        float sy1 = sy0 + (float)(TILE * SUPT - 1);
        int* cand = s_cand + (size_t)st * MAX_G;

        int cnt = 0;
        for (int g0 = 0; g0 < G; g0 += 4 * NTHREADS) {
            float4 Ar[4];
            bool hr[4];
            unsigned m[4];
#pragma unroll
            for (int r = 0; r < 4; r++) {
                int g = g0 + r * NTHREADS + tid;
                Ar[r] = (g < G) ? g_pA[g] : make_float4(1e30f, 1e30f, -1.f, 0.f);
            }
#pragma unroll
            for (int r = 0; r < 4; r++) {
                float ddx = fmaxf(fmaxf(sx0 - Ar[r].x, Ar[r].x - sx1), 0.f);
                float ddy = fmaxf(fmaxf(sy0 - Ar[r].y, Ar[r].y - sy1), 0.f);
                hr[r] = (ddx * ddx + ddy * ddy) <= Ar[r].z;
                m[r] = __ballot_sync(0xffffffffu, hr[r]);
            }
            if (lane == 0) {
#pragma unroll
                for (int r = 0; r < 4; r++) scnt[r * 4 + wid] = __popc(m[r]);
            }
            __syncthreads();
            // order = (round-major, warp-minor, lane): matches gaussian order
            int base = cnt, total = 0;
            int off = 0;
#pragma unroll
            for (int r = 0; r < 4; r++) {
#pragma unroll
                for (int w = 0; w < NW; w++) {
                    int cw = scnt[r * 4 + w];
                    if (r * 4 + w < wid + r * 4 && true) {}   // (no-op; clarity below)
                    total += cw;
                }
            }
            // compute this warp's offset for each round
#pragma unroll
            for (int r = 0; r < 4; r++) {
                int roff = base;
                for (int rr = 0; rr < r; rr++)
#pragma unroll
                    for (int w = 0; w < NW; w++) roff += scnt[rr * 4 + w];
                for (int w = 0; w < wid; w++) roff += scnt[r * 4 + w];
                if (hr[r]) cand[roff + __popc(m[r] & lmask)] = g0 + r * NTHREADS + tid;
            }
            cnt += total;
            __syncthreads();   // protect scnt reuse
        }
        if (tid == 0) s_cnt[st] = cnt;
    }

    grid_barrier(gridDim.x);

    // ================= Phase C: raster (block per 16x16 tile) =============
    if (blockIdx.x >= (unsigned)ntiles) return;

    int tile = blockIdx.x;
    int tx = tile % ntx, ty = tile / ntx;
    int lx = tid & (TILE - 1);
    int ly = tid >> 4;                     // rows ly and ly+8
    int px = tx * TILE + lx;
    int py = ty * TILE + ly;
    float fx = (float)px, fy = (float)py;

    float x0 = (float)(tx * TILE);
    float y0 = (float)(ty * TILE);
    float x1 = x0 + (float)(TILE - 1);
    float y1 = y0 + (float)(TILE - 1);

    int st = (ty >> 2) * nsx + (tx >> 2);  // 4x4 tiles per 64x64 supertile
    int n = s_cnt[st];
    const int* cand = s_cand + (size_t)st * MAX_G;

    float T1 = 1.f, r1 = 0.f, g1 = 0.f, b1 = 0.f;
    float T2 = 1.f, r2c = 0.f, g2c = 0.f, b2c = 0.f;

    for (int c0 = 0; c0 < n; c0 += NTHREADS) {
        int ci = c0 + tid;
        bool hit = false;
        int g = 0;
        float4 A;
        if (ci < n) {
            g = cand[ci];
            A = g_pA[g];
            float ddx = fmaxf(fmaxf(x0 - A.x, A.x - x1), 0.f);
            float ddy = fmaxf(fmaxf(y0 - A.y, A.y - y1), 0.f);
            hit = (ddx * ddx + ddy * ddy) <= A.z;
        }
        float4 B;
        float2 C;
        if (hit) {                          // early loads overlap ballot/prefix
            B = g_pB[g];
            C = g_pC[g];
        }
        unsigned m = __ballot_sync(0xffffffffu, hit);
        if (lane == 0) scnt[wid] = __popc(m);
        __syncthreads();                    // guards prev-chunk composite reads
        int woff = 0, total = 0;
#pragma unroll
        for (int w = 0; w < NW; w++) {
            int cw = scnt[w];
            woff += (w < wid) ? cw : 0;
            total += cw;
        }
        if (hit) {
            int idx = woff + __popc(m & lmask);
            sA[idx] = make_float4(A.x, A.y, A.w, B.x);   // mx,my,a',b'
            sB[idx] = make_float4(B.y, B.z, B.w, C.x);   // c',lop,cr,cg
            sC[idx] = C.y;                                // cb
        }
        __syncthreads();

#pragma unroll 4
        for (int j = 0; j < total; j++) {
            float4 Aj = sA[j];
            float4 Bj = sB[j];
            float  Cj = sC[j];
            float dx  = fx - Aj.x;
            float dy  = fy - Aj.y;
            float dy2 = dy + 8.f;
            float t0 = fmaf(Aj.z, dx * dx, Bj.y);
            float e1 = fmaf(Aj.w, dx * dy,  fmaf(Bj.x, dy  * dy,  t0));
            float e2 = fmaf(Aj.w, dx * dy2, fmaf(Bj.x, dy2 * dy2, t0));
            float a1 = fminf(ex2(e1), 0.99f);
            float a2 = fminf(ex2(e2), 0.99f);
            float w1 = T1 * a1;
            float w2 = T2 * a2;
            r1  = fmaf(w1, Bj.z, r1);   g1  = fmaf(w1, Bj.w, g1);   b1  = fmaf(w1, Cj, b1);
            r2c = fmaf(w2, Bj.z, r2c);  g2c = fmaf(w2, Bj.w, g2c);  b2c = fmaf(w2, Cj, b2c);
            T1 -= w1;
            T2 -= w2;
        }
    }

    if (px < W) {
        if (py < H) {
            int o = (py * W + px) * 3;
            out[o + 0] = r1; out[o + 1] = g1; out[o + 2] = b1;
        }
        if (py + 8 < H) {
            int o = ((py + 8) * W + px) * 3;
            out[o + 0] = r2c; out[o + 1] = g2c; out[o + 2] = b2c;
        }
    }
}

extern "C" void kernel_launch(void* const* d_in, const int* in_sizes, int n_in,
                              void* d_out, int out_size) {
    const float* means         = (const float*)d_in[0];
    const float* log_scale     = (const float*)d_in[1];
    const float* rot           = (const float*)d_in[2];
    const float* colour_logits = (const float*)d_in[3];
    const float* opacity_logit = (const float*)d_in[4];
    const float* depth         = (const float*)d_in[5];

    int G = in_sizes[5];
    if (G > MAX_G) G = MAX_G;

    int HW = out_size / 3;
    int W = (int)(sqrt((double)HW) + 0.5);
    if (W <= 0) W = 1;
    int H = HW / W;

    int ntx = (W + TILE - 1) / TILE;
    int nty = (H + TILE - 1) / TILE;
    int ntiles = ntx * nty;

    int nsx = (ntx + SUPT - 1) / SUPT;
    int nsy = (nty + SUPT - 1) / SUPT;
    int nsup = nsx * nsy;
    if (nsup > MAX_SUP) nsup = MAX_SUP;

    int nblocks = ntiles > 256 ? ntiles : 256;
    fused_kernel<<<nblocks, NTHREADS>>>(means, log_scale, rot, colour_logits,
                                        opacity_logit, depth,
                                        G, W, H, ntx, ntiles, nsx, nsup,
                                        (float*)d_out);
}

// round 16
// speedup vs baseline: 1.1707x; 1.1707x over previous
#include <cuda_runtime.h>
#include <math.h>

#define REG 32               // 32x32 pixel region per block
#define NTHREADS 256         // 32x8 threads; 4 pixels/thread (rows +0,+8,+16,+24)
#define NWB 8                // warps per block
#define MAX_G 2048
#define CHUNK 1024
#define ROUNDS (CHUNK / NTHREADS)   // 4
#define MAH_CUT 37.0f
#define LOG2E 1.4426950408889634f

// ---- depth-sorted packed gaussians (Phase A output) ----
__device__ float4 g_pA[MAX_G];   // mx, my, cullR^2, a' (= -0.5*iA*log2e)
__device__ float4 g_pB[MAX_G];   // b' (= -iB*log2e), c' (= -0.5*iC*log2e), log2(opac), colR
__device__ float2 g_pC[MAX_G];   // colG, colB

// ---- software grid barrier (replay-safe: generation is monotonic) ----
__device__ unsigned g_bar_count = 0;
__device__ volatile unsigned g_bar_gen = 0;

__device__ __forceinline__ void grid_barrier(unsigned nblocks) {
    __syncthreads();
    if (threadIdx.x == 0) {
        unsigned gen = g_bar_gen;
        __threadfence();
        unsigned old = atomicAdd(&g_bar_count, 1u);
        if (old == nblocks - 1u) {
            g_bar_count = 0;
            __threadfence();
            g_bar_gen = gen + 1u;
        } else {
            while (g_bar_gen == gen) __nanosleep(32);
        }
        __threadfence();
    }
    __syncthreads();
}

__device__ __forceinline__ float ex2(float x) {
    float r;
    asm("ex2.approx.ftz.f32 %0, %1;" : "=f"(r) : "f"(x));
    return r;
}

__global__ void __launch_bounds__(NTHREADS) fused_kernel(
        const float* __restrict__ means,
        const float* __restrict__ log_scale,
        const float* __restrict__ rot,
        const float* __restrict__ colour_logits,
        const float* __restrict__ opacity_logit,
        const float* __restrict__ depth,
        int G, int W, int H, int nrx, int nreg,
        float* __restrict__ out) {
    int tid  = threadIdx.x;
    int wid  = tid >> 5;
    int lane = tid & 31;
    unsigned lmask = (1u << lane) - 1u;

    __shared__ float4 sA[CHUNK];     // 16 KB
    __shared__ float4 sB[CHUNK];     // 16 KB
    __shared__ float  sC[CHUNK];     // 4 KB
    __shared__ int    scnt[ROUNDS * NWB];

    // ============ Phase A: warp-per-gaussian rank + preprocess ============
    for (int i = blockIdx.x * NWB + wid; i < G; i += gridDim.x * NWB) {
        float di = depth[i];
        int r = 0;
        for (int j = lane; j < G; j += 32) {
            float dj = depth[j];
            r += (dj < di) || (dj == di && j < i);
        }
        r = __reduce_add_sync(0xffffffffu, r);

        if (lane == 0) {
            float s2x = __expf(2.f * log_scale[2 * i + 0]);
            float s2y = __expf(2.f * log_scale[2 * i + 1]);
            float s, c;
            __sincosf(rot[i], &s, &c);

            float ca = c * c * s2x + s * s * s2y;
            float cb = c * s * (s2x - s2y);
            float cd = s * s * s2x + c * c * s2y;
            float det = ca * cd - cb * cb;
            float inv = 1.f / det;
            float iA = cd * inv;
            float iB = -cb * inv;
            float iC = ca * inv;

            float opac = 1.f / (1.f + __expf(-opacity_logit[i]));
            float cr  = 1.f / (1.f + __expf(-colour_logits[3 * i + 0]));
            float cg  = 1.f / (1.f + __expf(-colour_logits[3 * i + 1]));
            float cbl = 1.f / (1.f + __expf(-colour_logits[3 * i + 2]));

            float tr = 0.5f * (ca + cd);
            float lmax = tr + sqrtf(fmaxf(tr * tr - det, 0.f));

            g_pA[r] = make_float4(means[2 * i + 0], means[2 * i + 1],
                                  MAH_CUT * lmax, -0.5f * iA * LOG2E);
            g_pB[r] = make_float4(-iB * LOG2E, -0.5f * iC * LOG2E,
                                  __log2f(opac), cr);
            g_pC[r] = make_float2(cg, cbl);
        }
    }

    grid_barrier(gridDim.x);

    // ============ Phase C: one block per 32x32 region, 4 px/thread ========
    if (blockIdx.x >= (unsigned)nreg) return;

    int reg = blockIdx.x;
    int rx = reg % nrx, ry = reg / nrx;
    int px = rx * REG + (tid & 31);
    int py = ry * REG + (tid >> 5);          // rows py, py+8, py+16, py+24
    float fx = (float)px, fy = (float)py;

    float x0 = (float)(rx * REG);
    float y0 = (float)(ry * REG);
    float x1 = x0 + (float)(REG - 1);
    float y1 = y0 + (float)(REG - 1);

    float T0 = 1.f, T1 = 1.f, T2 = 1.f, T3 = 1.f;
    float aR0 = 0.f, aG0 = 0.f, aB0 = 0.f;
    float aR1 = 0.f, aG1 = 0.f, aB1 = 0.f;
    float aR2 = 0.f, aG2 = 0.f, aB2 = 0.f;
    float aR3 = 0.f, aG3 = 0.f, aB3 = 0.f;

    for (int c0 = 0; c0 < G; c0 += CHUNK) {
        // ---- prefetch cull data (independent LDG.128s) ----
        float4 Ar[ROUNDS];
        bool hr[ROUNDS];
#pragma unroll
        for (int r = 0; r < ROUNDS; r++) {
            int g = c0 + r * NTHREADS + tid;
            Ar[r] = (g < G) ? g_pA[g] : make_float4(1e30f, 1e30f, -1.f, 0.f);
        }
#pragma unroll
        for (int r = 0; r < ROUNDS; r++) {
            float ddx = fmaxf(fmaxf(x0 - Ar[r].x, Ar[r].x - x1), 0.f);
            float ddy = fmaxf(fmaxf(y0 - Ar[r].y, Ar[r].y - y1), 0.f);
            hr[r] = (ddx * ddx + ddy * ddy) <= Ar[r].z;
        }

        // early predicated loads: latency overlaps ballots/prefix/barrier
        float4 Br[ROUNDS];
        float2 Cr[ROUNDS];
#pragma unroll
        for (int r = 0; r < ROUNDS; r++) {
            if (hr[r]) {
                int g = c0 + r * NTHREADS + tid;
                Br[r] = g_pB[g];
                Cr[r] = g_pC[g];
            }
        }

        unsigned m[ROUNDS];
#pragma unroll
        for (int r = 0; r < ROUNDS; r++)
            m[r] = __ballot_sync(0xffffffffu, hr[r]);
        if (lane == 0) {
#pragma unroll
            for (int r = 0; r < ROUNDS; r++) scnt[r * NWB + wid] = __popc(m[r]);
        }
        __syncthreads();   // also guards prev-chunk composite reads

        // (round-major, warp-minor) exclusive prefix = depth order
        int offs[ROUNDS];
        int acc = 0;
#pragma unroll
        for (int r = 0; r < ROUNDS; r++) {
            int o = acc;
#pragma unroll
            for (int w = 0; w < NWB; w++) {
                int cw = scnt[r * NWB + w];
                if (w < wid) o += cw;
                acc += cw;
            }
            offs[r] = o;
        }
        int total = acc;

#pragma unroll
        for (int r = 0; r < ROUNDS; r++) {
            if (hr[r]) {
                int idx = offs[r] + __popc(m[r] & lmask);
                sA[idx] = make_float4(Ar[r].x, Ar[r].y, Ar[r].w, Br[r].x); // mx,my,a',b'
                sB[idx] = make_float4(Br[r].y, Br[r].z, Br[r].w, Cr[r].x); // c',lop,cr,cg
                sC[idx] = Cr[r].y;                                          // cb
            }
        }
        __syncthreads();

        // ---- single flat composite over compacted list (4 px/thread) ----
#pragma unroll 2
        for (int j = 0; j < total; j++) {
            float4 Aj = sA[j];
            float4 Bj = sB[j];
            float  Cj = sC[j];
            float dx  = fx - Aj.x;
            float dy0 = fy - Aj.y;
            float dy1 = dy0 + 8.f;
            float dy2 = dy0 + 16.f;
            float dy3 = dy0 + 24.f;
            float t0 = fmaf(Aj.z, dx * dx, Bj.y);   // a'*dx^2 + lop
            float u  = Aj.w * dx;                   // b'*dx
            float e0 = fmaf(Bj.x * dy0, dy0, fmaf(u, dy0, t0));
            float e1 = fmaf(Bj.x * dy1, dy1, fmaf(u, dy1, t0));
            float e2 = fmaf(Bj.x * dy2, dy2, fmaf(u, dy2, t0));
            float e3 = fmaf(Bj.x * dy3, dy3, fmaf(u, dy3, t0));
            float a0 = fminf(ex2(e0), 0.99f);
            float a1 = fminf(ex2(e1), 0.99f);
            float a2 = fminf(ex2(e2), 0.99f);
            float a3 = fminf(ex2(e3), 0.99f);
            float w0 = T0 * a0;
            float w1 = T1 * a1;
            float w2 = T2 * a2;
            float w3 = T3 * a3;
            aR0 = fmaf(w0, Bj.z, aR0); aG0 = fmaf(w0, Bj.w, aG0); aB0 = fmaf(w0, Cj, aB0);
            aR1 = fmaf(w1, Bj.z, aR1); aG1 = fmaf(w1, Bj.w, aG1); aB1 = fmaf(w1, Cj, aB1);
            aR2 = fmaf(w2, Bj.z, aR2); aG2 = fmaf(w2, Bj.w, aG2); aB2 = fmaf(w2, Cj, aB2);
            aR3 = fmaf(w3, Bj.z, aR3); aG3 = fmaf(w3, Bj.w, aG3); aB3 = fmaf(w3, Cj, aB3);
            T0 -= w0;
            T1 -= w1;
            T2 -= w2;
            T3 -= w3;
        }
    }

    if (px < W) {
        if (py < H) {
            int o = (py * W + px) * 3;
            out[o + 0] = aR0; out[o + 1] = aG0; out[o + 2] = aB0;
        }
        if (py + 8 < H) {
            int o = ((py + 8) * W + px) * 3;
            out[o + 0] = aR1; out[o + 1] = aG1; out[o + 2] = aB1;
        }
        if (py + 16 < H) {
            int o = ((py + 16) * W + px) * 3;
            out[o + 0] = aR2; out[o + 1] = aG2; out[o + 2] = aB2;
        }
        if (py + 24 < H) {
            int o = ((py + 24) * W + px) * 3;
            out[o + 0] = aR3; out[o + 1] = aG3; out[o + 2] = aB3;
        }
    }
}

extern "C" void kernel_launch(void* const* d_in, const int* in_sizes, int n_in,
                              void* d_out, int out_size) {
    const float* means         = (const float*)d_in[0];
    const float* log_scale     = (const float*)d_in[1];
    const float* rot           = (const float*)d_in[2];
    const float* colour_logits = (const float*)d_in[3];
    const float* opacity_logit = (const float*)d_in[4];
    const float* depth         = (const float*)d_in[5];

    int G = in_sizes[5];
    if (G > MAX_G) G = MAX_G;

    int HW = out_size / 3;
    int W = (int)(sqrt((double)HW) + 0.5);
    if (W <= 0) W = 1;
    int H = HW / W;

    int nrx = (W + REG - 1) / REG;
    int nry = (H + REG - 1) / REG;
    int nreg = nrx * nry;              // 144 for 384x384

    int nblocks = nreg;
    int needA = (G + NWB - 1) / NWB;
    if (nblocks < needA) nblocks = needA;

    fused_kernel<<<nblocks, NTHREADS>>>(means, log_scale, rot, colour_logits,
                                        opacity_logit, depth,
                                        G, W, H, nrx, nreg, (float*)d_out);
}